// round 6
// baseline (speedup 1.0000x reference)
#include <cuda_runtime.h>
#include <cuda_fp16.h>

// ---------------------------------------------------------------------------
// CustomGraphConv on GB300 — src-sorted formulation (R6)
//
//   msg[e,o]  = sum_{a,i} edge_attr[e,a] * W[a,o,i] * x[src_e, i]
//   aggr[n,o] = segment_sum over dst ; out = relu(aggr + bias)
//
// Pipeline:
//   P0 zero out + counters
//   P1 y[n][o][a] = sum_i W[a,o,i] x[n,i]  (fp16 store, [o][a] layout)
//   P2 histogram of src
//   P3 exclusive scan -> per-src edge ranges (single-block)
//   P4 scatter (dst, eattr) into src-sorted arrays
//   P5 warp-per-src-node: load y once (256B), stream edges (even/odd to the
//      two half-warps), red.global.add.v4.f32 to out[dst]
//   P6 relu(out + bias)
//
// Why: R4 proved edge phase wasn't pure gather-BW bound; the 16x redundant
// per-edge y refetch (410MB of L2) is removed entirely (26MB, once per node).
// ---------------------------------------------------------------------------

#define MAX_NODES 100000
#define MAX_EDGES 1600000

__device__ __half g_yh[MAX_NODES * 128];      // 25.6 MB, layout [n][o=16][a=8]
__device__ int    g_cnt[MAX_NODES];
__device__ int    g_off[MAX_NODES + 1];
__device__ int    g_cur[MAX_NODES];
__device__ int    g_dst_s[MAX_EDGES];
__device__ float  g_ea_s[MAX_EDGES * 8];      // 51.2 MB, src-sorted eattr

// ---------------------------------------------------------------------------
// P0a: zero output (harness poisons d_out with 0xAA)
// ---------------------------------------------------------------------------
__global__ void zero_out_kernel(float4* __restrict__ out, int n4) {
    int i = blockIdx.x * blockDim.x + threadIdx.x;
    if (i < n4) out[i] = make_float4(0.f, 0.f, 0.f, 0.f);
}

// P0b: zero histogram counters
__global__ void zero_cnt_kernel(int N) {
    int i = blockIdx.x * blockDim.x + threadIdx.x;
    if (i < N) g_cnt[i] = 0;
}

// ---------------------------------------------------------------------------
// P1: thread-per-node precompute. y[n][o][a] = dot(W[a][o][:], x[n][:]).
// W loads warp-uniform (broadcast, L1-resident after first touch).
// Output: per o, 8 a-values packed into one uint4 (8 fp16 = 16B).
// ---------------------------------------------------------------------------
__global__ void precompute_y_kernel(const float* __restrict__ x,
                                    const float* __restrict__ W,
                                    int N) {
    int n = blockIdx.x * blockDim.x + threadIdx.x;
    if (n >= N) return;

    const float4* x4 = (const float4*)(x + (long long)n * 16);
    float4 x0 = x4[0], x1 = x4[1], x2 = x4[2], x3 = x4[3];

    const float4* W4 = (const float4*)W;          // row (a,o) at (a*16+o)*4
    uint4* yp = (uint4*)g_yh + (long long)n * 16; // one uint4 per o

#pragma unroll 4
    for (int o = 0; o < 16; ++o) {
        float acc[8];
#pragma unroll
        for (int a = 0; a < 8; ++a) {
            int row = a * 16 + o;
            float4 w0 = W4[row * 4 + 0];
            float4 w1 = W4[row * 4 + 1];
            float4 w2 = W4[row * 4 + 2];
            float4 w3 = W4[row * 4 + 3];
            float v;
            v  = w0.x * x0.x + w0.y * x0.y + w0.z * x0.z + w0.w * x0.w;
            v += w1.x * x1.x + w1.y * x1.y + w1.z * x1.z + w1.w * x1.w;
            v += w2.x * x2.x + w2.y * x2.y + w2.z * x2.z + w2.w * x2.w;
            v += w3.x * x3.x + w3.y * x3.y + w3.z * x3.z + w3.w * x3.w;
            acc[a] = v;
        }
        __half2 h0 = __floats2half2_rn(acc[0], acc[1]);
        __half2 h1 = __floats2half2_rn(acc[2], acc[3]);
        __half2 h2 = __floats2half2_rn(acc[4], acc[5]);
        __half2 h3 = __floats2half2_rn(acc[6], acc[7]);
        uint4 u;
        u.x = *(unsigned*)&h0;
        u.y = *(unsigned*)&h1;
        u.z = *(unsigned*)&h2;
        u.w = *(unsigned*)&h3;
        yp[o] = u;
    }
}

// ---------------------------------------------------------------------------
// P2: src histogram (edge_index is int32: src = ei[e], dst = ei[E+e])
// ---------------------------------------------------------------------------
__global__ void hist_kernel(const int* __restrict__ ei, int E) {
    int e = blockIdx.x * blockDim.x + threadIdx.x;
    if (e < E) atomicAdd(&g_cnt[ei[e]], 1);
}

// ---------------------------------------------------------------------------
// P3: exclusive scan of g_cnt -> g_off / g_cur. Single block, 1024 threads:
// per-thread chunk sums, Hillis-Steele block scan, then chunk walk.
// ---------------------------------------------------------------------------
__global__ void scan_kernel(int N, int E) {
    __shared__ int part[1024];
    int t = threadIdx.x;
    int chunk = (N + 1023) / 1024;
    int beg = t * chunk;
    int end = beg + chunk; if (end > N) end = N;

    int s = 0;
    for (int i = beg; i < end; ++i) s += g_cnt[i];
    part[t] = s;
    __syncthreads();

    for (int d = 1; d < 1024; d <<= 1) {
        int v = (t >= d) ? part[t - d] : 0;
        __syncthreads();
        part[t] += v;
        __syncthreads();
    }

    int run = (t == 0) ? 0 : part[t - 1];
    for (int i = beg; i < end; ++i) {
        g_off[i] = run;
        g_cur[i] = run;
        run += g_cnt[i];
    }
    if (t == 0) g_off[N] = E;
}

// ---------------------------------------------------------------------------
// P4: scatter edges into src-sorted order (dst + eattr rows)
// ---------------------------------------------------------------------------
__global__ void scatter_kernel(const int* __restrict__ ei,
                               const float* __restrict__ eattr,
                               int E) {
    int e = blockIdx.x * blockDim.x + threadIdx.x;
    if (e >= E) return;
    int s = ei[e];
    int p = atomicAdd(&g_cur[s], 1);
    g_dst_s[p] = ei[E + e];
    float4 a0 = ((const float4*)eattr)[e * 2];
    float4 a1 = ((const float4*)eattr)[e * 2 + 1];
    ((float4*)g_ea_s)[p * 2]     = a0;
    ((float4*)g_ea_s)[p * 2 + 1] = a1;
}

// ---------------------------------------------------------------------------
// P5: warp per src node. lane = h*16 + o (h = half-warp, o = out channel).
// Load y[n][o][:8] once (16B/lane, both halves read same 2 lines).
// Half h processes edges beg+h, beg+h+2, ... (counts differ by <=1: balanced;
// halves may diverge so shfl masks are per-half, and shfl_down stays inside
// the half for all consumers o%4==0).
// Per edge: 8 FMA -> msg[o] in lane o; 3 shfl assemble float4; red.v4.
// ---------------------------------------------------------------------------
__global__ void edge_kernel(float* __restrict__ out, int N) {
    int lane = threadIdx.x & 31;
    int warp = (blockIdx.x * blockDim.x + threadIdx.x) >> 5;
    if (warp >= N) return;
    int n = warp;
    int o = lane & 15;
    int h = lane >> 4;
    unsigned hm = 0xFFFFu << (h * 16);

    uint4 t = ((const uint4*)g_yh)[(long long)n * 16 + o];
    const __half2* hp = (const __half2*)&t;
    float ya[8];
#pragma unroll
    for (int q = 0; q < 4; ++q) {
        float2 f = __half22float2(hp[q]);
        ya[2 * q]     = f.x;
        ya[2 * q + 1] = f.y;
    }

    int beg = g_off[n];
    int end = g_off[n + 1];

    for (int i = beg + h; i < end; i += 2) {
        float4 e0 = ((const float4*)g_ea_s)[i * 2];
        float4 e1 = ((const float4*)g_ea_s)[i * 2 + 1];
        float m = ya[0] * e0.x + ya[1] * e0.y + ya[2] * e0.z + ya[3] * e0.w
                + ya[4] * e1.x + ya[5] * e1.y + ya[6] * e1.z + ya[7] * e1.w;
        int dst = g_dst_s[i];

        float r1 = __shfl_down_sync(hm, m, 1);
        float r2 = __shfl_down_sync(hm, m, 2);
        float r3 = __shfl_down_sync(hm, m, 3);

        if ((o & 3) == 0) {
            float* p = out + (long long)dst * 16 + o;
            asm volatile("red.global.add.v4.f32 [%0], {%1, %2, %3, %4};"
                         :: "l"(p), "f"(m), "f"(r1), "f"(r2), "f"(r3)
                         : "memory");
        }
    }
}

// ---------------------------------------------------------------------------
// P6: out = relu(out + bias)
// ---------------------------------------------------------------------------
__global__ void bias_relu_kernel(float* __restrict__ out,
                                 const float* __restrict__ bias,
                                 int total4) {
    int i = blockIdx.x * blockDim.x + threadIdx.x;
    if (i >= total4) return;
    float4 v = ((float4*)out)[i];
    float4 b = ((const float4*)bias)[i & 3];
    v.x = fmaxf(v.x + b.x, 0.f);
    v.y = fmaxf(v.y + b.y, 0.f);
    v.z = fmaxf(v.z + b.z, 0.f);
    v.w = fmaxf(v.w + b.w, 0.f);
    ((float4*)out)[i] = v;
}

// ---------------------------------------------------------------------------
// inputs (metadata order): x[N,16] f32, edge_index[2,E] i32, edge_attr[E,8]
//   f32, weight_matrix[8,16,16] f32, bias[16] f32, num_nodes
// output: [N,16] f32
// ---------------------------------------------------------------------------
extern "C" void kernel_launch(void* const* d_in, const int* in_sizes, int n_in,
                              void* d_out, int out_size) {
    const float* x = (const float*)d_in[0];
    const int* ei = (const int*)d_in[1];
    const float* eattr = (const float*)d_in[2];
    const float* W = (const float*)d_in[3];
    const float* bias = (const float*)d_in[4];

    int N = in_sizes[0] / 16;
    int E = in_sizes[2] / 8;
    float* out = (float*)d_out;

    // P0: zero out + counters
    {
        int n4 = out_size / 4;
        zero_out_kernel<<<(n4 + 255) / 256, 256>>>((float4*)out, n4);
        zero_cnt_kernel<<<(N + 255) / 256, 256>>>(N);
    }
    // P1: per-node precompute
    precompute_y_kernel<<<(N + 255) / 256, 256>>>(x, W, N);
    // P2: src histogram
    hist_kernel<<<(E + 255) / 256, 256>>>(ei, E);
    // P3: scan
    scan_kernel<<<1, 1024>>>(N, E);
    // P4: scatter into src-sorted order
    scatter_kernel<<<(E + 255) / 256, 256>>>(ei, eattr, E);
    // P5: warp-per-node edge processing
    {
        long long threads = (long long)N * 32;
        int blocks = (int)((threads + 255) / 256);
        edge_kernel<<<blocks, 256>>>(out, N);
    }
    // P6: bias + relu
    {
        int total4 = out_size / 4;
        bias_relu_kernel<<<(total4 + 255) / 256, 256>>>(out, bias, total4);
    }
}

// round 7
// speedup vs baseline: 2.7775x; 2.7775x over previous
#include <cuda_runtime.h>
#include <cuda_fp16.h>

// ---------------------------------------------------------------------------
// CustomGraphConv on GB300 — R7: revert to R5 (best: 117.2us), launch-order
// rearranged so the edge kernel lands in the profiled slot (#4).
//
//   msg[e,o]  = sum_{a,i} edge_attr[e,a] * W[a,o,i] * x[src_e, i]
//   aggr[n,o] = segment_sum over dst ; out = relu(aggr + bias)
//
// Factorized:
//   P1 y[n,j] = sum_i W[j,i] x[n,i] (j=a*16+o flattened), fp16 store.
//   P2 8 lanes/edge gather y_h[src] (2x128B lines = 2 wavefronts/edge),
//      fp32 accumulate, red.global.add.v4.f32 scatter to out[dst].
//   P3 relu(out + bias)
//
// R6 lesson: src-sorting (hist+scan+scatter) costs >>200us; the redundant
// per-edge y refetch is cheaper than materializing sorted copies.
// ---------------------------------------------------------------------------

#define MAX_NODES 100000

__device__ __half g_yh[MAX_NODES * 128];   // 25.6 MB (L2-resident)

// ---------------------------------------------------------------------------
// zero halves of out (harness poisons d_out with 0xAA). Split in two so the
// edge kernel is launch #4 (the slot ncu captures).
// ---------------------------------------------------------------------------
__global__ void zero_out_kernel(float4* __restrict__ out, int base, int n4) {
    int i = base + blockIdx.x * blockDim.x + threadIdx.x;
    if (i < n4) out[i] = make_float4(0.f, 0.f, 0.f, 0.f);
}

// ---------------------------------------------------------------------------
// P1: thread-per-node. y[n][j] = dot(W[j][:], x[n][:]), j in [0,128).
// W loads are warp-uniform -> single broadcast wavefront each, L1-resident.
// 8 independent FMA chains per chunk; half2-packed 16B stores.
// ---------------------------------------------------------------------------
__global__ void precompute_y_kernel(const float* __restrict__ x,
                                    const float* __restrict__ W,
                                    int N) {
    int n = blockIdx.x * blockDim.x + threadIdx.x;
    if (n >= N) return;

    const float4* x4 = (const float4*)(x + (long long)n * 16);
    float4 x0 = x4[0], x1 = x4[1], x2 = x4[2], x3 = x4[3];

    const float4* W4 = (const float4*)W;              // row j at W4[j*4 + q]
    uint4* yp = (uint4*)(g_yh + (long long)n * 128);  // 16B per 8-output chunk

#pragma unroll 4
    for (int jc = 0; jc < 16; ++jc) {
        float acc[8];
#pragma unroll
        for (int jj = 0; jj < 8; ++jj) {
            int j = jc * 8 + jj;
            float4 w0 = W4[j * 4 + 0];
            float4 w1 = W4[j * 4 + 1];
            float4 w2 = W4[j * 4 + 2];
            float4 w3 = W4[j * 4 + 3];
            float a;
            a  = w0.x * x0.x + w0.y * x0.y + w0.z * x0.z + w0.w * x0.w;
            a += w1.x * x1.x + w1.y * x1.y + w1.z * x1.z + w1.w * x1.w;
            a += w2.x * x2.x + w2.y * x2.y + w2.z * x2.z + w2.w * x2.w;
            a += w3.x * x3.x + w3.y * x3.y + w3.z * x3.z + w3.w * x3.w;
            acc[jj] = a;
        }
        __half2 h0 = __floats2half2_rn(acc[0], acc[1]);
        __half2 h1 = __floats2half2_rn(acc[2], acc[3]);
        __half2 h2 = __floats2half2_rn(acc[4], acc[5]);
        __half2 h3 = __floats2half2_rn(acc[6], acc[7]);
        uint4 u;
        u.x = *(unsigned*)&h0;
        u.y = *(unsigned*)&h1;
        u.z = *(unsigned*)&h2;
        u.w = *(unsigned*)&h3;
        yp[jc] = u;
    }
}

// ---------------------------------------------------------------------------
// P2: 8 lanes per edge, 8 edges per warp (x2 loop for ILP/MLP).
// y_h viewed as uint4[16] per node; lane s loads chunks {s, s+8}: the 8
// lanes of an edge cover one contiguous 128B line per k -> 2 wavefronts/edge.
// Chunk j holds (a = j>>1, o = (j&1)*8 + t); lane s accumulates o-half
// p = s&1 over a = 4k + (s>>1). shfl_xor(2),(4) folds; lanes s<2 issue
// 2x red.global.add.v4.f32. edge_index int32: src = ei[e], dst = ei[E+e].
// ---------------------------------------------------------------------------
__global__ void edge_scatter_kernel(const int* __restrict__ ei,
                                    const float* __restrict__ eattr,
                                    float* __restrict__ out,
                                    int E) {
    int lane = threadIdx.x & 31;
    int warp = (blockIdx.x * blockDim.x + threadIdx.x) >> 5;
    int g = lane >> 3;   // edge slot within warp (0..3)
    int s = lane & 7;    // sublane within edge

#pragma unroll
    for (int t = 0; t < 2; ++t) {
        int e = warp * 8 + t * 4 + g;
        if (e >= E) break;  // uniform across the 8-lane group

        int src = ei[e];
        const uint4* yv = (const uint4*)g_yh + (long long)src * 16;
        const float* ea = eattr + (long long)e * 8;

        float acc[8];
#pragma unroll
        for (int i = 0; i < 8; ++i) acc[i] = 0.f;

#pragma unroll
        for (int k = 0; k < 2; ++k) {
            uint4 v = yv[k * 8 + s];          // 8 lanes -> one 128B line
            float w = ea[4 * k + (s >> 1)];   // a = 4k + (s>>1)
            const __half2* h = (const __half2*)&v;
#pragma unroll
            for (int q = 0; q < 4; ++q) {
                float2 f = __half22float2(h[q]);
                acc[2 * q]     += w * f.x;
                acc[2 * q + 1] += w * f.y;
            }
        }

        unsigned mask = __activemask();
#pragma unroll
        for (int i = 0; i < 8; ++i) {
            acc[i] += __shfl_xor_sync(mask, acc[i], 2);
            acc[i] += __shfl_xor_sync(mask, acc[i], 4);
        }

        if (s < 2) {
            int dst = ei[E + e];
            float* p = out + (long long)dst * 16 + s * 8;
            asm volatile("red.global.add.v4.f32 [%0], {%1, %2, %3, %4};"
                         :: "l"(p), "f"(acc[0]), "f"(acc[1]), "f"(acc[2]), "f"(acc[3])
                         : "memory");
            asm volatile("red.global.add.v4.f32 [%0], {%1, %2, %3, %4};"
                         :: "l"(p + 4), "f"(acc[4]), "f"(acc[5]), "f"(acc[6]), "f"(acc[7])
                         : "memory");
        }
    }
}

// ---------------------------------------------------------------------------
// P3: out = relu(out + bias)
// ---------------------------------------------------------------------------
__global__ void bias_relu_kernel(float* __restrict__ out,
                                 const float* __restrict__ bias,
                                 int total4) {
    int i = blockIdx.x * blockDim.x + threadIdx.x;
    if (i >= total4) return;
    float4 v = ((float4*)out)[i];
    float4 b = ((const float4*)bias)[i & 3];
    v.x = fmaxf(v.x + b.x, 0.f);
    v.y = fmaxf(v.y + b.y, 0.f);
    v.z = fmaxf(v.z + b.z, 0.f);
    v.w = fmaxf(v.w + b.w, 0.f);
    ((float4*)out)[i] = v;
}

// ---------------------------------------------------------------------------
// inputs (metadata order): x[N,16] f32, edge_index[2,E] i32, edge_attr[E,8]
//   f32, weight_matrix[8,16,16] f32, bias[16] f32, num_nodes
// output: [N,16] f32
//
// Launch order chosen so edge_scatter_kernel is launch #4 (ncu's slot):
//   1 zeroA   2 precompute   3 zeroB   4 edge   5 bias
// ---------------------------------------------------------------------------
extern "C" void kernel_launch(void* const* d_in, const int* in_sizes, int n_in,
                              void* d_out, int out_size) {
    const float* x = (const float*)d_in[0];
    const int* ei = (const int*)d_in[1];
    const float* eattr = (const float*)d_in[2];
    const float* W = (const float*)d_in[3];
    const float* bias = (const float*)d_in[4];

    int N = in_sizes[0] / 16;
    int E = in_sizes[2] / 8;
    float* out = (float*)d_out;

    int n4 = out_size / 4;
    int half4 = n4 / 2;

    // 1: zero first half of out
    zero_out_kernel<<<(half4 + 255) / 256, 256>>>((float4*)out, 0, half4);
    // 2: per-node precompute
    precompute_y_kernel<<<(N + 255) / 256, 256>>>(x, W, N);
    // 3: zero second half of out
    zero_out_kernel<<<((n4 - half4) + 255) / 256, 256>>>((float4*)out, half4, n4);
    // 4: edge gather/scatter  (profiled slot)
    {
        long long warps = ((long long)E + 7) / 8;
        long long threads = warps * 32;
        int blocks = (int)((threads + 255) / 256);
        edge_scatter_kernel<<<blocks, 256>>>(ei, eattr, out, E);
    }
    // 5: bias + relu
    bias_relu_kernel<<<(n4 + 255) / 256, 256>>>(out, bias, n4);
}

// round 8
// speedup vs baseline: 2.9099x; 1.0477x over previous
#include <cuda_runtime.h>
#include <cuda_fp16.h>

// ---------------------------------------------------------------------------
// CustomGraphConv on GB300 — R8: single-red-instruction scatter.
//
//   msg[e,o]  = sum_{a,i} edge_attr[e,a] * W[a,o,i] * x[src_e, i]
//   aggr[n,o] = segment_sum over dst ; out = relu(aggr + bias)
//
// R7 profile: edge kernel L1tex=75.6% (binding). Atomic scatter was issuing
// 2 red.v4 instructions per edge-quad, each touching the SAME 4 dst lines ->
// every line paid twice. Now lanes s=0..3 (which all hold complete folded
// sums) each issue ONE red.v4 on a distinct quad: atomic wavefronts halved
// (16 -> 8 per warp), total warp wavefronts 40 -> 32.
// ---------------------------------------------------------------------------

#define MAX_NODES 100000

__device__ __half g_yh[MAX_NODES * 128];   // 25.6 MB (L2-resident)

// ---------------------------------------------------------------------------
// zero halves of out (harness poisons d_out with 0xAA). Split so the edge
// kernel stays launch #4 (the ncu slot).
// ---------------------------------------------------------------------------
__global__ void zero_out_kernel(float4* __restrict__ out, int base, int n4) {
    int i = base + blockIdx.x * blockDim.x + threadIdx.x;
    if (i < n4) out[i] = make_float4(0.f, 0.f, 0.f, 0.f);
}

// ---------------------------------------------------------------------------
// P1: thread-per-node. y[n][j] = dot(W[j][:], x[n][:]), j in [0,128).
// W loads warp-uniform (broadcast, L1-resident). half2-packed 16B stores.
// ---------------------------------------------------------------------------
__global__ void precompute_y_kernel(const float* __restrict__ x,
                                    const float* __restrict__ W,
                                    int N) {
    int n = blockIdx.x * blockDim.x + threadIdx.x;
    if (n >= N) return;

    const float4* x4 = (const float4*)(x + (long long)n * 16);
    float4 x0 = x4[0], x1 = x4[1], x2 = x4[2], x3 = x4[3];

    const float4* W4 = (const float4*)W;              // row j at W4[j*4 + q]
    uint4* yp = (uint4*)(g_yh + (long long)n * 128);  // 16B per 8-output chunk

#pragma unroll 4
    for (int jc = 0; jc < 16; ++jc) {
        float acc[8];
#pragma unroll
        for (int jj = 0; jj < 8; ++jj) {
            int j = jc * 8 + jj;
            float4 w0 = W4[j * 4 + 0];
            float4 w1 = W4[j * 4 + 1];
            float4 w2 = W4[j * 4 + 2];
            float4 w3 = W4[j * 4 + 3];
            float a;
            a  = w0.x * x0.x + w0.y * x0.y + w0.z * x0.z + w0.w * x0.w;
            a += w1.x * x1.x + w1.y * x1.y + w1.z * x1.z + w1.w * x1.w;
            a += w2.x * x2.x + w2.y * x2.y + w2.z * x2.z + w2.w * x2.w;
            a += w3.x * x3.x + w3.y * x3.y + w3.z * x3.z + w3.w * x3.w;
            acc[jj] = a;
        }
        __half2 h0 = __floats2half2_rn(acc[0], acc[1]);
        __half2 h1 = __floats2half2_rn(acc[2], acc[3]);
        __half2 h2 = __floats2half2_rn(acc[4], acc[5]);
        __half2 h3 = __floats2half2_rn(acc[6], acc[7]);
        uint4 u;
        u.x = *(unsigned*)&h0;
        u.y = *(unsigned*)&h1;
        u.z = *(unsigned*)&h2;
        u.w = *(unsigned*)&h3;
        yp[jc] = u;
    }
}

// ---------------------------------------------------------------------------
// P2: 8 lanes per edge, 8 edges per warp (x2 loop).
// Lane s loads y-chunks {s, s+8}: one 128B line per k -> 2 wavefronts/edge.
// Chunk j holds (a = j>>1, o = (j&1)*8 + t); lane s covers o-half p = s&1,
// a = 4k + (s>>1). xor2+xor4 folds the 4 lanes of each half -> ALL lanes
// hold complete sums for their half. Lanes s<4 then each issue ONE
// red.global.add.v4.f32 on a distinct quad of the 64B dst row:
//   s=0 -> o[0:4]   s=2 -> o[4:8]   s=1 -> o[8:12]   s=3 -> o[12:16]
// => one red instruction per edge-quad per t (4 dst lines paid once).
// ---------------------------------------------------------------------------
__global__ void edge_scatter_kernel(const int* __restrict__ ei,
                                    const float* __restrict__ eattr,
                                    float* __restrict__ out,
                                    int E) {
    int lane = threadIdx.x & 31;
    int warp = (blockIdx.x * blockDim.x + threadIdx.x) >> 5;
    int g = lane >> 3;   // edge slot within warp (0..3)
    int s = lane & 7;    // sublane within edge

#pragma unroll
    for (int t = 0; t < 2; ++t) {
        int e = warp * 8 + t * 4 + g;
        if (e >= E) break;  // uniform across the 8-lane group

        int src = ei[e];
        const uint4* yv = (const uint4*)g_yh + (long long)src * 16;
        const float* ea = eattr + (long long)e * 8;

        float acc[8];
#pragma unroll
        for (int i = 0; i < 8; ++i) acc[i] = 0.f;

#pragma unroll
        for (int k = 0; k < 2; ++k) {
            uint4 v = yv[k * 8 + s];          // 8 lanes -> one 128B line
            float w = ea[4 * k + (s >> 1)];   // a = 4k + (s>>1)
            const __half2* h = (const __half2*)&v;
#pragma unroll
            for (int q = 0; q < 4; ++q) {
                float2 f = __half22float2(h[q]);
                acc[2 * q]     += w * f.x;
                acc[2 * q + 1] += w * f.y;
            }
        }

        unsigned mask = __activemask();
#pragma unroll
        for (int i = 0; i < 8; ++i) {
            acc[i] += __shfl_xor_sync(mask, acc[i], 2);
            acc[i] += __shfl_xor_sync(mask, acc[i], 4);
        }

        if (s < 4) {
            int dst = ei[E + e];
            // s&1 selects o-half (0..7 vs 8..15); s>>1 selects quad within it.
            int hi = (s >> 1) & 1;           // 0 -> acc[0..3], 1 -> acc[4..7]
            float v0 = hi ? acc[4] : acc[0];
            float v1 = hi ? acc[5] : acc[1];
            float v2 = hi ? acc[6] : acc[2];
            float v3 = hi ? acc[7] : acc[3];
            float* p = out + (long long)dst * 16 + (s & 1) * 8 + hi * 4;
            asm volatile("red.global.add.v4.f32 [%0], {%1, %2, %3, %4};"
                         :: "l"(p), "f"(v0), "f"(v1), "f"(v2), "f"(v3)
                         : "memory");
        }
    }
}

// ---------------------------------------------------------------------------
// P3: out = relu(out + bias)
// ---------------------------------------------------------------------------
__global__ void bias_relu_kernel(float* __restrict__ out,
                                 const float* __restrict__ bias,
                                 int total4) {
    int i = blockIdx.x * blockDim.x + threadIdx.x;
    if (i >= total4) return;
    float4 v = ((float4*)out)[i];
    float4 b = ((const float4*)bias)[i & 3];
    v.x = fmaxf(v.x + b.x, 0.f);
    v.y = fmaxf(v.y + b.y, 0.f);
    v.z = fmaxf(v.z + b.z, 0.f);
    v.w = fmaxf(v.w + b.w, 0.f);
    ((float4*)out)[i] = v;
}

// ---------------------------------------------------------------------------
// inputs (metadata order): x[N,16] f32, edge_index[2,E] i32, edge_attr[E,8]
//   f32, weight_matrix[8,16,16] f32, bias[16] f32, num_nodes
// output: [N,16] f32
//
// Launch order: 1 zeroA  2 precompute  3 zeroB  4 edge (ncu slot)  5 bias
// ---------------------------------------------------------------------------
extern "C" void kernel_launch(void* const* d_in, const int* in_sizes, int n_in,
                              void* d_out, int out_size) {
    const float* x = (const float*)d_in[0];
    const int* ei = (const int*)d_in[1];
    const float* eattr = (const float*)d_in[2];
    const float* W = (const float*)d_in[3];
    const float* bias = (const float*)d_in[4];

    int N = in_sizes[0] / 16;
    int E = in_sizes[2] / 8;
    float* out = (float*)d_out;

    int n4 = out_size / 4;
    int half4 = n4 / 2;

    // 1: zero first half of out
    zero_out_kernel<<<(half4 + 255) / 256, 256>>>((float4*)out, 0, half4);
    // 2: per-node precompute
    precompute_y_kernel<<<(N + 255) / 256, 256>>>(x, W, N);
    // 3: zero second half of out
    zero_out_kernel<<<((n4 - half4) + 255) / 256, 256>>>((float4*)out, half4, n4);
    // 4: edge gather/scatter  (profiled slot)
    {
        long long warps = ((long long)E + 7) / 8;
        long long threads = warps * 32;
        int blocks = (int)((threads + 255) / 256);
        edge_scatter_kernel<<<blocks, 256>>>(ei, eattr, out, E);
    }
    // 5: bias + relu
    bias_relu_kernel<<<(n4 + 255) / 256, 256>>>(out, bias, n4);
}

// round 9
// speedup vs baseline: 3.9924x; 1.3720x over previous
#include <cuda_runtime.h>
#include <cuda_fp16.h>

// ---------------------------------------------------------------------------
// CustomGraphConv on GB300 — R9: shfl-free edge kernel (o-major y) +
// 4-nodes-per-thread precompute.
//
//   msg[e,o]  = sum_{a,i} edge_attr[e,a] * W[a,o,i] * x[src_e, i]
//   aggr[n,o] = segment_sum over dst ; out = relu(aggr + bias)
//
// R8 lessons: (a) SHFL shares the MIO/L1tex path — the fold tree was half
// the L1 pressure; o-major y layout makes the a-reduction a register dot.
// (b) thread-per-node precompute re-loads W 512x per thread (~40us); 4-node
// amortization cuts W LDGs 4x.
// ---------------------------------------------------------------------------

#define MAX_NODES 100000

// layout: [n][o=16][a=8] fp16 -> one uint4 (16B) per (n,o). 25.6 MB.
__device__ __half g_yh[MAX_NODES * 128];

// ---------------------------------------------------------------------------
// zero halves of out (harness poisons d_out). Split keeps edge kernel at
// launch #4 (the ncu capture slot).
// ---------------------------------------------------------------------------
__global__ void zero_out_kernel(float4* __restrict__ out, int base, int n4) {
    int i = base + blockIdx.x * blockDim.x + threadIdx.x;
    if (i < n4) out[i] = make_float4(0.f, 0.f, 0.f, 0.f);
}

// ---------------------------------------------------------------------------
// P1: y[n][o][a] = dot(W[a][o][:], x[n][:]). Each thread computes 4 nodes
// (lane-strided: n0, n0+32, n0+64, n0+96) so each warp-uniform W row load
// is amortized over 4 nodes. Per thread: 128 W LDG.128 (broadcast), 8192
// FFMA, 64 coalesced STG.128.
// ---------------------------------------------------------------------------
__global__ void __launch_bounds__(128)
precompute_y_kernel(const float* __restrict__ x,
                    const float* __restrict__ W,
                    int N) {
    int lane = threadIdx.x & 31;
    int warp = (blockIdx.x * blockDim.x + threadIdx.x) >> 5;
    int n0 = warp * 128 + lane;

    float4 xv[4][4];
    int nidx[4];
#pragma unroll
    for (int nn = 0; nn < 4; ++nn) {
        int n = n0 + 32 * nn;
        if (n >= N) n = N - 1;       // duplicate writes of same data: benign
        nidx[nn] = n;
        const float4* xp = (const float4*)x + (long long)n * 4;
#pragma unroll
        for (int q = 0; q < 4; ++q) xv[nn][q] = xp[q];
    }

    const float4* W4 = (const float4*)W;   // row (a,o) at index (a*16+o)*4

#pragma unroll 2
    for (int o = 0; o < 16; ++o) {
        float acc[4][8];
#pragma unroll
        for (int a = 0; a < 8; ++a) {
            int row = a * 16 + o;
            float4 w0 = W4[row * 4 + 0];
            float4 w1 = W4[row * 4 + 1];
            float4 w2 = W4[row * 4 + 2];
            float4 w3 = W4[row * 4 + 3];
#pragma unroll
            for (int nn = 0; nn < 4; ++nn) {
                float v;
                v  = w0.x * xv[nn][0].x + w0.y * xv[nn][0].y
                   + w0.z * xv[nn][0].z + w0.w * xv[nn][0].w;
                v += w1.x * xv[nn][1].x + w1.y * xv[nn][1].y
                   + w1.z * xv[nn][1].z + w1.w * xv[nn][1].w;
                v += w2.x * xv[nn][2].x + w2.y * xv[nn][2].y
                   + w2.z * xv[nn][2].z + w2.w * xv[nn][2].w;
                v += w3.x * xv[nn][3].x + w3.y * xv[nn][3].y
                   + w3.z * xv[nn][3].z + w3.w * xv[nn][3].w;
                acc[nn][a] = v;
            }
        }
#pragma unroll
        for (int nn = 0; nn < 4; ++nn) {
            __half2 h0 = __floats2half2_rn(acc[nn][0], acc[nn][1]);
            __half2 h1 = __floats2half2_rn(acc[nn][2], acc[nn][3]);
            __half2 h2 = __floats2half2_rn(acc[nn][4], acc[nn][5]);
            __half2 h3 = __floats2half2_rn(acc[nn][6], acc[nn][7]);
            uint4 u;
            u.x = *(unsigned*)&h0;
            u.y = *(unsigned*)&h1;
            u.z = *(unsigned*)&h2;
            u.w = *(unsigned*)&h3;
            ((uint4*)g_yh)[(long long)nidx[nn] * 16 + o] = u;
        }
    }
}

// ---------------------------------------------------------------------------
// P2: 8 lanes/edge, 4 edges/warp, x2 loop (8 edges/warp).
// Lane s loads y chunks {s, s+8}: each LDG covers one 128B line per edge
// (2 wavefronts/edge = gather minimum). Chunk o holds all 8 a-values ->
// lane computes complete msg[o=s] and msg[o=s+8] as register dots with
// ea[e][0..8] (two broadcast float4 loads). ZERO shfl.
// Scatter: two scalar red.global.add.f32 per lane (dst row bytes [0,32) and
// [32,64) across the 8 lanes of the edge).
// ---------------------------------------------------------------------------
__global__ void edge_scatter_kernel(const int* __restrict__ ei,
                                    const float* __restrict__ eattr,
                                    float* __restrict__ out,
                                    int E) {
    int lane = threadIdx.x & 31;
    int warp = (blockIdx.x * blockDim.x + threadIdx.x) >> 5;
    int g = lane >> 3;   // edge slot within warp (0..3)
    int s = lane & 7;    // sublane within edge = base o

#pragma unroll
    for (int t = 0; t < 2; ++t) {
        int e = warp * 8 + t * 4 + g;
        if (e >= E) break;  // uniform across the 8-lane group

        int src = ei[e];
        const uint4* yv = (const uint4*)g_yh + (long long)src * 16;
        const float4* ea4 = (const float4*)(eattr + (long long)e * 8);
        float4 ea0 = ea4[0];
        float4 ea1 = ea4[1];

        uint4 v0 = yv[s];        // o = s      (lanes 0..7 -> one 128B line)
        uint4 v1 = yv[s + 8];    // o = s + 8  (second line)

        float m0, m1;
        {
            const __half2* h = (const __half2*)&v0;
            float2 f0 = __half22float2(h[0]);
            float2 f1 = __half22float2(h[1]);
            float2 f2 = __half22float2(h[2]);
            float2 f3 = __half22float2(h[3]);
            m0 = f0.x * ea0.x + f0.y * ea0.y + f1.x * ea0.z + f1.y * ea0.w
               + f2.x * ea1.x + f2.y * ea1.y + f3.x * ea1.z + f3.y * ea1.w;
        }
        {
            const __half2* h = (const __half2*)&v1;
            float2 f0 = __half22float2(h[0]);
            float2 f1 = __half22float2(h[1]);
            float2 f2 = __half22float2(h[2]);
            float2 f3 = __half22float2(h[3]);
            m1 = f0.x * ea0.x + f0.y * ea0.y + f1.x * ea0.z + f1.y * ea0.w
               + f2.x * ea1.x + f2.y * ea1.y + f3.x * ea1.z + f3.y * ea1.w;
        }

        int dst = ei[E + e];
        float* p = out + (long long)dst * 16;
        asm volatile("red.global.add.f32 [%0], %1;"
                     :: "l"(p + s), "f"(m0) : "memory");
        asm volatile("red.global.add.f32 [%0], %1;"
                     :: "l"(p + s + 8), "f"(m1) : "memory");
    }
}

// ---------------------------------------------------------------------------
// P3: out = relu(out + bias)
// ---------------------------------------------------------------------------
__global__ void bias_relu_kernel(float* __restrict__ out,
                                 const float* __restrict__ bias,
                                 int total4) {
    int i = blockIdx.x * blockDim.x + threadIdx.x;
    if (i >= total4) return;
    float4 v = ((float4*)out)[i];
    float4 b = ((const float4*)bias)[i & 3];
    v.x = fmaxf(v.x + b.x, 0.f);
    v.y = fmaxf(v.y + b.y, 0.f);
    v.z = fmaxf(v.z + b.z, 0.f);
    v.w = fmaxf(v.w + b.w, 0.f);
    ((float4*)out)[i] = v;
}

// ---------------------------------------------------------------------------
// inputs (metadata order): x[N,16] f32, edge_index[2,E] i32, edge_attr[E,8]
//   f32, weight_matrix[8,16,16] f32, bias[16] f32, num_nodes
// output: [N,16] f32
//
// Launch order: 1 zeroA  2 precompute  3 zeroB  4 edge (ncu slot)  5 bias
// ---------------------------------------------------------------------------
extern "C" void kernel_launch(void* const* d_in, const int* in_sizes, int n_in,
                              void* d_out, int out_size) {
    const float* x = (const float*)d_in[0];
    const int* ei = (const int*)d_in[1];
    const float* eattr = (const float*)d_in[2];
    const float* W = (const float*)d_in[3];
    const float* bias = (const float*)d_in[4];

    int N = in_sizes[0] / 16;
    int E = in_sizes[2] / 8;
    float* out = (float*)d_out;

    int n4 = out_size / 4;
    int half4 = n4 / 2;

    // 1: zero first half of out
    zero_out_kernel<<<(half4 + 255) / 256, 256>>>((float4*)out, 0, half4);
    // 2: per-node precompute (4 nodes/thread, 128 nodes/warp)
    {
        long long warps = ((long long)N + 127) / 128;
        long long threads = warps * 32;
        int blocks = (int)((threads + 127) / 128);
        precompute_y_kernel<<<blocks, 128>>>(x, W, N);
    }
    // 3: zero second half of out
    zero_out_kernel<<<((n4 - half4) + 255) / 256, 256>>>((float4*)out, half4, n4);
    // 4: edge gather/scatter  (profiled slot)
    {
        long long warps = ((long long)E + 7) / 8;
        long long threads = warps * 32;
        int blocks = (int)((threads + 255) / 256);
        edge_scatter_kernel<<<blocks, 256>>>(ei, eattr, out, E);
    }
    // 5: bias + relu
    bias_relu_kernel<<<(n4 + 255) / 256, 256>>>(out, bias, n4);
}

// round 10
// speedup vs baseline: 4.0745x; 1.0206x over previous
#include <cuda_runtime.h>
#include <cuda_fp16.h>

// ---------------------------------------------------------------------------
// CustomGraphConv on GB300 — R10: parity-permuted y layout -> red.v2 scatter.
//
//   msg[e,o]  = sum_{a,i} edge_attr[e,a] * W[a,o,i] * x[src_e, i]
//   aggr[n,o] = segment_sum over dst ; out = relu(aggr + bias)
//
// Edge warp wavefront audit (R9): 5/edge = gather 2 (minimal) + red 2 +
// ea/idx 1. Scalar reds wrote o=s and o=s+8 (32B apart, unmergeable).
// New chunk order c(o) = (o&1)*8 + (o>>1): line0 = even o, line1 = odd o.
// Lane s loads chunks {s, s+8} (same 2-wavefront gather) but now holds
// m[2s], m[2s+1] -> ONE red.global.add.v2.f32. 40 -> 32 wavefronts/warp.
//
// out is initialized to bias (atomics add on top); final pass = pure relu.
// ---------------------------------------------------------------------------

#define MAX_NODES 100000

// layout: [n][c=16][a=8] fp16, chunk c holds o = (c<8) ? 2c : 2(c-8)+1
__device__ __half g_yh[MAX_NODES * 128];   // 25.6 MB (L2-resident)

// ---------------------------------------------------------------------------
// init halves of out with bias (harness poisons d_out with 0xAA). Split so
// the edge kernel stays launch #4 (the ncu capture slot).
// ---------------------------------------------------------------------------
__global__ void init_out_kernel(float4* __restrict__ out,
                                const float* __restrict__ bias,
                                int base, int n4) {
    int i = base + blockIdx.x * blockDim.x + threadIdx.x;
    if (i < n4) out[i] = ((const float4*)bias)[i & 3];
}

// ---------------------------------------------------------------------------
// P1: y[n][c(o)][a] = dot(W[a][o][:], x[n][:]). 4 nodes per thread
// (lane-strided) so warp-uniform W row loads amortize 4x.
// ---------------------------------------------------------------------------
__global__ void __launch_bounds__(128)
precompute_y_kernel(const float* __restrict__ x,
                    const float* __restrict__ W,
                    int N) {
    int lane = threadIdx.x & 31;
    int warp = (blockIdx.x * blockDim.x + threadIdx.x) >> 5;
    int n0 = warp * 128 + lane;

    float4 xv[4][4];
    int nidx[4];
#pragma unroll
    for (int nn = 0; nn < 4; ++nn) {
        int n = n0 + 32 * nn;
        if (n >= N) n = N - 1;       // duplicate writes of same data: benign
        nidx[nn] = n;
        const float4* xp = (const float4*)x + (long long)n * 4;
#pragma unroll
        for (int q = 0; q < 4; ++q) xv[nn][q] = xp[q];
    }

    const float4* W4 = (const float4*)W;   // row (a,o) at index (a*16+o)*4

#pragma unroll 2
    for (int o = 0; o < 16; ++o) {
        float acc[4][8];
#pragma unroll
        for (int a = 0; a < 8; ++a) {
            int row = a * 16 + o;
            float4 w0 = W4[row * 4 + 0];
            float4 w1 = W4[row * 4 + 1];
            float4 w2 = W4[row * 4 + 2];
            float4 w3 = W4[row * 4 + 3];
#pragma unroll
            for (int nn = 0; nn < 4; ++nn) {
                float v;
                v  = w0.x * xv[nn][0].x + w0.y * xv[nn][0].y
                   + w0.z * xv[nn][0].z + w0.w * xv[nn][0].w;
                v += w1.x * xv[nn][1].x + w1.y * xv[nn][1].y
                   + w1.z * xv[nn][1].z + w1.w * xv[nn][1].w;
                v += w2.x * xv[nn][2].x + w2.y * xv[nn][2].y
                   + w2.z * xv[nn][2].z + w2.w * xv[nn][2].w;
                v += w3.x * xv[nn][3].x + w3.y * xv[nn][3].y
                   + w3.z * xv[nn][3].z + w3.w * xv[nn][3].w;
                acc[nn][a] = v;
            }
        }
        // parity-permuted chunk: even o -> chunks 0..7, odd o -> chunks 8..15
        int c = (o & 1) * 8 + (o >> 1);
#pragma unroll
        for (int nn = 0; nn < 4; ++nn) {
            __half2 h0 = __floats2half2_rn(acc[nn][0], acc[nn][1]);
            __half2 h1 = __floats2half2_rn(acc[nn][2], acc[nn][3]);
            __half2 h2 = __floats2half2_rn(acc[nn][4], acc[nn][5]);
            __half2 h3 = __floats2half2_rn(acc[nn][6], acc[nn][7]);
            uint4 u;
            u.x = *(unsigned*)&h0;
            u.y = *(unsigned*)&h1;
            u.z = *(unsigned*)&h2;
            u.w = *(unsigned*)&h3;
            ((uint4*)g_yh)[(long long)nidx[nn] * 16 + c] = u;
        }
    }
}

// ---------------------------------------------------------------------------
// P2: 8 lanes/edge, 4 edges/warp, x2 loop (8 edges/warp).
// Lane s loads chunks {s, s+8}: one 128B line each (2 wavefronts/edge).
// Chunk s   = o=2s   (all 8 a-values); chunk s+8 = o=2s+1.
// Register dot with ea[e][0..8] (broadcast float4 x2). ZERO shfl.
// Scatter: ONE red.global.add.v2.f32 per lane at out[dst][2s].
// ---------------------------------------------------------------------------
__global__ void edge_scatter_kernel(const int* __restrict__ ei,
                                    const float* __restrict__ eattr,
                                    float* __restrict__ out,
                                    int E) {
    int lane = threadIdx.x & 31;
    int warp = (blockIdx.x * blockDim.x + threadIdx.x) >> 5;
    int g = lane >> 3;   // edge slot within warp (0..3)
    int s = lane & 7;    // sublane within edge

#pragma unroll
    for (int t = 0; t < 2; ++t) {
        int e = warp * 8 + t * 4 + g;
        if (e >= E) break;  // uniform across the 8-lane group

        int src = ei[e];
        const uint4* yv = (const uint4*)g_yh + (long long)src * 16;
        const float4* ea4 = (const float4*)(eattr + (long long)e * 8);
        float4 ea0 = ea4[0];
        float4 ea1 = ea4[1];

        uint4 v0 = yv[s];        // o = 2s    (lanes 0..7 -> line 0)
        uint4 v1 = yv[s + 8];    // o = 2s+1  (lanes 0..7 -> line 1)

        float m0, m1;
        {
            const __half2* h = (const __half2*)&v0;
            float2 f0 = __half22float2(h[0]);
            float2 f1 = __half22float2(h[1]);
            float2 f2 = __half22float2(h[2]);
            float2 f3 = __half22float2(h[3]);
            m0 = f0.x * ea0.x + f0.y * ea0.y + f1.x * ea0.z + f1.y * ea0.w
               + f2.x * ea1.x + f2.y * ea1.y + f3.x * ea1.z + f3.y * ea1.w;
        }
        {
            const __half2* h = (const __half2*)&v1;
            float2 f0 = __half22float2(h[0]);
            float2 f1 = __half22float2(h[1]);
            float2 f2 = __half22float2(h[2]);
            float2 f3 = __half22float2(h[3]);
            m1 = f0.x * ea0.x + f0.y * ea0.y + f1.x * ea0.z + f1.y * ea0.w
               + f2.x * ea1.x + f2.y * ea1.y + f3.x * ea1.z + f3.y * ea1.w;
        }

        int dst = ei[E + e];
        float* p = out + (long long)dst * 16 + 2 * s;
        asm volatile("red.global.add.v2.f32 [%0], {%1, %2};"
                     :: "l"(p), "f"(m0), "f"(m1) : "memory");
    }
}

// ---------------------------------------------------------------------------
// P3: out = relu(out)   (bias already folded into the init)
// ---------------------------------------------------------------------------
__global__ void relu_kernel(float* __restrict__ out, int total4) {
    int i = blockIdx.x * blockDim.x + threadIdx.x;
    if (i >= total4) return;
    float4 v = ((float4*)out)[i];
    v.x = fmaxf(v.x, 0.f);
    v.y = fmaxf(v.y, 0.f);
    v.z = fmaxf(v.z, 0.f);
    v.w = fmaxf(v.w, 0.f);
    ((float4*)out)[i] = v;
}

// ---------------------------------------------------------------------------
// inputs (metadata order): x[N,16] f32, edge_index[2,E] i32, edge_attr[E,8]
//   f32, weight_matrix[8,16,16] f32, bias[16] f32, num_nodes
// output: [N,16] f32
//
// Launch order: 1 initA  2 precompute  3 initB  4 edge (ncu slot)  5 relu
// ---------------------------------------------------------------------------
extern "C" void kernel_launch(void* const* d_in, const int* in_sizes, int n_in,
                              void* d_out, int out_size) {
    const float* x = (const float*)d_in[0];
    const int* ei = (const int*)d_in[1];
    const float* eattr = (const float*)d_in[2];
    const float* W = (const float*)d_in[3];
    const float* bias = (const float*)d_in[4];

    int N = in_sizes[0] / 16;
    int E = in_sizes[2] / 8;
    float* out = (float*)d_out;

    int n4 = out_size / 4;
    int half4 = n4 / 2;

    // 1: init first half of out with bias
    init_out_kernel<<<(half4 + 255) / 256, 256>>>((float4*)out, bias, 0, half4);
    // 2: per-node precompute (4 nodes/thread)
    {
        long long warps = ((long long)N + 127) / 128;
        long long threads = warps * 32;
        int blocks = (int)((threads + 127) / 128);
        precompute_y_kernel<<<blocks, 128>>>(x, W, N);
    }
    // 3: init second half of out with bias
    init_out_kernel<<<((n4 - half4) + 255) / 256, 256>>>((float4*)out, bias, half4, n4);
    // 4: edge gather/scatter  (profiled slot)
    {
        long long warps = ((long long)E + 7) / 8;
        long long threads = warps * 32;
        int blocks = (int)((threads + 255) / 256);
        edge_scatter_kernel<<<blocks, 256>>>(ei, eattr, out, E);
    }
    // 5: relu
    relu_kernel<<<(n4 + 255) / 256, 256>>>(out, n4);
}